// round 11
// baseline (speedup 1.0000x reference)
#include <cuda_runtime.h>
#include <cuda_bf16.h>
#include <stdint.h>
#include <math.h>

#define TT 8
#define NN 50000
#define EE 800000
#define FF 128
#define HH 128
#define SCAN_BLOCKS ((NN + 255) / 256)   // 196

// ---------------- device scratch (no allocs allowed) ----------------
__device__ float g_agg[(size_t)NN * HH];
__device__ float g_bufA[(size_t)NN * HH];
__device__ float g_bufB[(size_t)NN * HH];
__device__ int   g_cnt[TT][NN];
__device__ int   g_off[TT][NN + 1];
__device__ int   g_cur[TT][NN];
__device__ int   g_csr[TT][EE];
__device__ int   g_bsum[TT][SCAN_BLOCKS];
__device__ int   g_bbase[TT][SCAN_BLOCKS];
__device__ float g_inv[TT][NN];
__device__ float g_pooled[TT * HH];

// ---------------- packed f32x2 helpers ----------------
__device__ __forceinline__ unsigned long long pack_dup(float a) {
    unsigned long long r;
    unsigned int au = __float_as_uint(a);
    asm("mov.b64 %0, {%1, %1};" : "=l"(r) : "r"(au));
    return r;
}
__device__ __forceinline__ void ffma2(unsigned long long& acc, unsigned long long a,
                                      unsigned long long b) {
    asm("fma.rn.f32x2 %0, %1, %2, %3;" : "=l"(acc) : "l"(a), "l"(b), "l"(acc));
}
__device__ __forceinline__ void unpack2(unsigned long long v, float& lo, float& hi) {
    unsigned int l, h;
    asm("mov.b64 {%0, %1}, %2;" : "=r"(l), "=r"(h) : "l"(v));
    lo = __uint_as_float(l);
    hi = __uint_as_float(h);
}

// ---------------- batched CSR utility kernels ----------------
__global__ void zero_all_kernel(int* __restrict__ p, int n) {
    int i = blockIdx.x * blockDim.x + threadIdx.x;
    if (i < n) p[i] = 0;
}
__global__ void zero_f4_kernel(float4* __restrict__ p, int n4) {
    int i = blockIdx.x * blockDim.x + threadIdx.x;
    if (i < n4) p[i] = make_float4(0.f, 0.f, 0.f, 0.f);
}

// all timesteps at once: cnt[t][dst]++
__global__ void deg_all_kernel(const int* __restrict__ ei, int* __restrict__ cntB) {
    int g = blockIdx.x * blockDim.x + threadIdx.x;
    if (g >= TT * EE) return;
    int t = g / EE;
    int e = g - t * EE;
    int d = ei[(size_t)t * 2 * EE + EE + e];
    atomicAdd(&cntB[t * NN + d], 1);
}

__global__ void scan_reduce_all_kernel(const int* __restrict__ cntB, int* __restrict__ bsumB) {
    __shared__ int wsum[8];
    int t = blockIdx.x / SCAN_BLOCKS;
    int blk = blockIdx.x - t * SCAN_BLOCKS;
    int i = blk * 256 + threadIdx.x;
    int v = (i < NN) ? cntB[t * NN + i] : 0;
    int lane = threadIdx.x & 31, wid = threadIdx.x >> 5;
    int s = v;
#pragma unroll
    for (int o = 16; o > 0; o >>= 1) s += __shfl_down_sync(0xffffffffu, s, o);
    if (lane == 0) wsum[wid] = s;
    __syncthreads();
    if (threadIdx.x == 0) {
        int tot = 0;
#pragma unroll
        for (int w = 0; w < 8; w++) tot += wsum[w];
        bsumB[t * SCAN_BLOCKS + blk] = tot;
    }
}

// grid = TT; each block scans its timestep's SCAN_BLOCKS partials
__global__ void scan_top_all_kernel(const int* __restrict__ bsumB, int* __restrict__ bbaseB) {
    __shared__ int wsum[8];
    int t = blockIdx.x;
    int tid = threadIdx.x;
    int v = (tid < SCAN_BLOCKS) ? bsumB[t * SCAN_BLOCKS + tid] : 0;
    int lane = tid & 31, wid = tid >> 5;
    int s = v;
#pragma unroll
    for (int o = 1; o < 32; o <<= 1) {
        int u = __shfl_up_sync(0xffffffffu, s, o);
        if (lane >= o) s += u;
    }
    if (lane == 31) wsum[wid] = s;
    __syncthreads();
    if (wid == 0) {
        int ws = (lane < 8) ? wsum[lane] : 0;
#pragma unroll
        for (int o = 1; o < 8; o <<= 1) {
            int u = __shfl_up_sync(0xffffffffu, ws, o);
            if (lane >= o) ws += u;
        }
        if (lane < 8) wsum[lane] = ws;
    }
    __syncthreads();
    int incl = s + (wid > 0 ? wsum[wid - 1] : 0);
    if (tid < SCAN_BLOCKS) bbaseB[t * SCAN_BLOCKS + tid] = incl - v;
}

__global__ void scan_final_all_kernel(const int* __restrict__ cntB, const int* __restrict__ bbaseB,
                                      int* __restrict__ offB, int* __restrict__ curB,
                                      float* __restrict__ invB) {
    __shared__ int wsum[8];
    int t = blockIdx.x / SCAN_BLOCKS;
    int blk = blockIdx.x - t * SCAN_BLOCKS;
    int i = blk * 256 + threadIdx.x;
    int v = (i < NN) ? cntB[t * NN + i] : 0;
    int lane = threadIdx.x & 31, wid = threadIdx.x >> 5;
    int s = v;
#pragma unroll
    for (int o = 1; o < 32; o <<= 1) {
        int u = __shfl_up_sync(0xffffffffu, s, o);
        if (lane >= o) s += u;
    }
    if (lane == 31) wsum[wid] = s;
    __syncthreads();
    if (wid == 0) {
        int ws = (lane < 8) ? wsum[lane] : 0;
#pragma unroll
        for (int o = 1; o < 8; o <<= 1) {
            int u = __shfl_up_sync(0xffffffffu, ws, o);
            if (lane >= o) ws += u;
        }
        if (lane < 8) wsum[lane] = ws;
    }
    __syncthreads();
    int excl = s - v + (wid > 0 ? wsum[wid - 1] : 0) + bbaseB[t * SCAN_BLOCKS + blk];
    if (i < NN) {
        offB[t * (NN + 1) + i] = excl;
        curB[t * NN + i] = excl;
        invB[t * NN + i] = 1.0f / (float)(v > 0 ? v : 1);
    }
    if (i == NN - 1) offB[t * (NN + 1) + NN] = excl + v;
}

__global__ void fill_all_kernel(const int* __restrict__ ei, int* __restrict__ curB,
                                int* __restrict__ csrB) {
    int g = blockIdx.x * blockDim.x + threadIdx.x;
    if (g >= TT * EE) return;
    int t = g / EE;
    int e = g - t * EE;
    const int* base = ei + (size_t)t * 2 * EE;
    int srcv = base[e];
    int d = base[EE + e];
    int p = atomicAdd(&curB[t * NN + d], 1);
    csrB[(size_t)t * EE + p] = srcv;
}

// ---------------- fused agg + SAGE GEMM ----------------
// Phase A: this CTA gathers/means its 128 rows of agg into aggG (global scratch).
// Phase B: out = relu(aggS @ Wl + x @ Wr + b), FFMA2 + ping-pong double buffer.
template<bool POOL>
__global__ __launch_bounds__(256, 2)
void sage_fused_kernel(const float* __restrict__ x,     // input features (also A2)
                       const int* __restrict__ off,
                       const int* __restrict__ csr,
                       const float* __restrict__ inv,
                       float* __restrict__ aggG,        // scratch (this CTA's rows only)
                       const float* __restrict__ Wl,
                       const float* __restrict__ Wr,
                       const float* __restrict__ bias,
                       float* __restrict__ out,
                       int n) {
    __shared__ float As[2][16][128];
    __shared__ float Bs[2][16][128];

    int tid = threadIdx.x;
    int wid = tid >> 5;
    int lane = tid & 31;
    int row0 = blockIdx.x * 128;

    // ---------- phase A: gather-aggregate 128 rows (16 per warp) ----------
#pragma unroll 1
    for (int rr = 0; rr < 16; rr++) {
        int node = row0 + wid * 16 + rr;
        if (node >= n) break;
        int e = off[node];
        int e1 = off[node + 1];
        float4 acc = make_float4(0.f, 0.f, 0.f, 0.f);
        for (; e + 1 < e1; e += 2) {
            int s0 = csr[e];
            int s1 = csr[e + 1];
            float4 v0 = ((const float4*)(x + (size_t)s0 * HH))[lane];
            float4 v1 = ((const float4*)(x + (size_t)s1 * HH))[lane];
            acc.x += v0.x + v1.x;
            acc.y += v0.y + v1.y;
            acc.z += v0.z + v1.z;
            acc.w += v0.w + v1.w;
        }
        if (e < e1) {
            int s0 = csr[e];
            float4 v0 = ((const float4*)(x + (size_t)s0 * HH))[lane];
            acc.x += v0.x; acc.y += v0.y; acc.z += v0.z; acc.w += v0.w;
        }
        float sc = inv[node];
        acc.x *= sc; acc.y *= sc; acc.z *= sc; acc.w *= sc;
        ((float4*)(aggG + (size_t)node * HH))[lane] = acc;
    }
    __syncthreads();

    // ---------- phase B: GEMM ----------
    int tx = tid & 15;        // col group (8 cols = 4 f32x2)
    int ty = tid >> 4;        // row group (8 rows)
    int li = tid >> 2;        // A row 0..63 (+64)
    int lk = (tid & 3) * 4;   // A k sub
    int bk = tid >> 5;        // B k 0..7 (+8)
    int bj = (tid & 31) * 4;  // B col

    unsigned long long acc2[8][4];
#pragma unroll
    for (int r = 0; r < 8; r++)
#pragma unroll
        for (int c = 0; c < 4; c++) acc2[r][c] = 0ull;

    float4 rA0, rA1, rB0, rB1;

#define GLOAD(kt) do { \
        int k0 = (kt) * 16; \
        const float* Asrc = (k0 < 128) ? aggG : x; \
        const float* Wsrc = (k0 < 128) ? Wl : Wr; \
        int ksrc = (k0 < 128) ? k0 : (k0 - 128); \
        int gi0 = row0 + li; \
        int gi1 = gi0 + 64; \
        rA0 = make_float4(0.f, 0.f, 0.f, 0.f); \
        rA1 = make_float4(0.f, 0.f, 0.f, 0.f); \
        if (gi0 < n) rA0 = *(const float4*)&Asrc[(size_t)gi0 * 128 + ksrc + lk]; \
        if (gi1 < n) rA1 = *(const float4*)&Asrc[(size_t)gi1 * 128 + ksrc + lk]; \
        rB0 = *(const float4*)&Wsrc[(size_t)(ksrc + bk) * 128 + bj]; \
        rB1 = *(const float4*)&Wsrc[(size_t)(ksrc + bk + 8) * 128 + bj]; \
    } while (0)

#define SSTORE(kt) do { \
        int b = (kt) & 1; \
        As[b][lk + 0][li] = rA0.x; As[b][lk + 1][li] = rA0.y; \
        As[b][lk + 2][li] = rA0.z; As[b][lk + 3][li] = rA0.w; \
        As[b][lk + 0][li + 64] = rA1.x; As[b][lk + 1][li + 64] = rA1.y; \
        As[b][lk + 2][li + 64] = rA1.z; As[b][lk + 3][li + 64] = rA1.w; \
        *(float4*)&Bs[b][bk][bj] = rB0; \
        *(float4*)&Bs[b][bk + 8][bj] = rB1; \
    } while (0)

    GLOAD(0);
    SSTORE(0);

#pragma unroll 1
    for (int kt = 0; kt < 16; kt++) {
        if (kt < 15) GLOAD(kt + 1);
        __syncthreads();
        int b = kt & 1;
#pragma unroll
        for (int k = 0; k < 16; k++) {
            float a[8];
            *(float4*)&a[0] = *(const float4*)&As[b][k][ty * 8];
            *(float4*)&a[4] = *(const float4*)&As[b][k][ty * 8 + 4];
            unsigned long long b2[4];
            const unsigned long long* bp = (const unsigned long long*)&Bs[b][k][tx * 8];
            b2[0] = bp[0]; b2[1] = bp[1]; b2[2] = bp[2]; b2[3] = bp[3];
#pragma unroll
            for (int r = 0; r < 8; r++) {
                unsigned long long aa = pack_dup(a[r]);
                ffma2(acc2[r][0], aa, b2[0]);
                ffma2(acc2[r][1], aa, b2[1]);
                ffma2(acc2[r][2], aa, b2[2]);
                ffma2(acc2[r][3], aa, b2[3]);
            }
        }
        if (kt < 15) SSTORE(kt + 1);
    }
    __syncthreads();

    float bv[8];
    *(float4*)&bv[0] = *(const float4*)&bias[tx * 8];
    *(float4*)&bv[4] = *(const float4*)&bias[tx * 8 + 4];

    if (!POOL) {
#pragma unroll
        for (int r = 0; r < 8; r++) {
            int gi = row0 + ty * 8 + r;
            if (gi < n) {
                float o[8];
#pragma unroll
                for (int c = 0; c < 4; c++) {
                    float lo, hi;
                    unpack2(acc2[r][c], lo, hi);
                    o[2 * c]     = fmaxf(lo + bv[2 * c], 0.f);
                    o[2 * c + 1] = fmaxf(hi + bv[2 * c + 1], 0.f);
                }
                *(float4*)&out[(size_t)gi * 128 + tx * 8]     = *(float4*)&o[0];
                *(float4*)&out[(size_t)gi * 128 + tx * 8 + 4] = *(float4*)&o[4];
            }
        }
    } else {
        float colsum[8];
#pragma unroll
        for (int c = 0; c < 8; c++) colsum[c] = 0.f;
#pragma unroll
        for (int r = 0; r < 8; r++) {
            int gi = row0 + ty * 8 + r;
            if (gi < n) {
#pragma unroll
                for (int c = 0; c < 4; c++) {
                    float lo, hi;
                    unpack2(acc2[r][c], lo, hi);
                    colsum[2 * c]     += fmaxf(lo + bv[2 * c], 0.f);
                    colsum[2 * c + 1] += fmaxf(hi + bv[2 * c + 1], 0.f);
                }
            }
        }
        float* red = &As[0][0][0];
        *(float4*)&red[ty * 128 + tx * 8]     = *(float4*)&colsum[0];
        *(float4*)&red[ty * 128 + tx * 8 + 4] = *(float4*)&colsum[4];
        __syncthreads();
        if (ty == 0) {
#pragma unroll
            for (int c = 0; c < 8; c++) {
                float s = 0.f;
#pragma unroll
                for (int g = 0; g < 16; g++) s += red[g * 128 + tx * 8 + c];
                atomicAdd(&out[tx * 8 + c], s);
            }
        }
    }
#undef GLOAD
#undef SSTORE
}

// ---------------- head: attention (only last q row) + MLP + sigmoid ----------------
__global__ void head_kernel(const float* __restrict__ pooled,
                            const float* __restrict__ Wq, const float* __restrict__ bq,
                            const float* __restrict__ Wk, const float* __restrict__ bk,
                            const float* __restrict__ Wv, const float* __restrict__ bv,
                            const float* __restrict__ Wo, const float* __restrict__ bo,
                            const float* __restrict__ Wh1, const float* __restrict__ bh1,
                            const float* __restrict__ Wh2, const float* __restrict__ bh2,
                            float* __restrict__ out) {
    __shared__ float seq[TT][HH];
    __shared__ float kk_s[TT][HH];
    __shared__ float vv_s[TT][HH];
    __shared__ float qv[HH];
    __shared__ float sc[4][TT];
    __shared__ float ol[HH];
    __shared__ float zz[HH];
    __shared__ float h1s[64];

    int j = threadIdx.x;  // 0..127
    const float invN = 1.0f / (float)NN;

    for (int t = 0; t < TT; t++) seq[t][j] = pooled[t * HH + j] * invN;
    __syncthreads();

    {
        float aq = bq[j];
        for (int k = 0; k < HH; k++) aq += seq[TT - 1][k] * Wq[k * HH + j];
        qv[j] = aq;
        for (int t = 0; t < TT; t++) {
            float ak = bk[j], av = bv[j];
            for (int k = 0; k < HH; k++) {
                float s = seq[t][k];
                ak += s * Wk[k * HH + j];
                av += s * Wv[k * HH + j];
            }
            kk_s[t][j] = ak;
            vv_s[t][j] = av;
        }
    }
    __syncthreads();

    if (j < 32) {
        int h = j >> 3, t = j & 7;
        float s = 0.f;
        for (int d = 0; d < 32; d++) s += qv[h * 32 + d] * kk_s[t][h * 32 + d];
        sc[h][t] = s * 0.17677669529663687f;
    }
    __syncthreads();
    if (j < 4) {
        float m = sc[j][0];
        for (int t = 1; t < TT; t++) m = fmaxf(m, sc[j][t]);
        float s = 0.f;
        for (int t = 0; t < TT; t++) { float e = expf(sc[j][t] - m); sc[j][t] = e; s += e; }
        float r = 1.0f / s;
        for (int t = 0; t < TT; t++) sc[j][t] *= r;
    }
    __syncthreads();

    {
        int h = j >> 5;
        float o = 0.f;
        for (int t = 0; t < TT; t++) o += sc[h][t] * vv_s[t][j];
        ol[j] = o;
    }
    __syncthreads();

    {
        float a = bo[j];
        for (int k = 0; k < HH; k++) a += ol[k] * Wo[k * HH + j];
        zz[j] = a;
    }
    __syncthreads();

    if (j < 64) {
        float a = bh1[j];
        for (int k = 0; k < HH; k++) a += zz[k] * Wh1[k * 64 + j];
        h1s[j] = fmaxf(a, 0.f);
    }
    __syncthreads();

    if (j == 0) {
        float a = bh2[0];
        for (int k = 0; k < 64; k++) a += h1s[k] * Wh2[k];
        out[0] = 1.0f / (1.0f + expf(-a));
    }
}

// ---------------- host ----------------
extern "C" void kernel_launch(void* const* d_in, const int* in_sizes, int n_in,
                              void* d_out, int out_size) {
    const float* xs  = (const float*)d_in[0];
    const int*   ei  = (const int*)d_in[1];
    const float* Wl1 = (const float*)d_in[2];
    const float* Wr1 = (const float*)d_in[3];
    const float* b1  = (const float*)d_in[4];
    const float* Wl2 = (const float*)d_in[5];
    const float* Wr2 = (const float*)d_in[6];
    const float* b2  = (const float*)d_in[7];
    const float* Wl3 = (const float*)d_in[8];
    const float* Wr3 = (const float*)d_in[9];
    const float* b3  = (const float*)d_in[10];
    const float* Wq  = (const float*)d_in[11];
    const float* bq  = (const float*)d_in[12];
    const float* Wk  = (const float*)d_in[13];
    const float* bk  = (const float*)d_in[14];
    const float* Wv  = (const float*)d_in[15];
    const float* bv  = (const float*)d_in[16];
    const float* Wo  = (const float*)d_in[17];
    const float* bo  = (const float*)d_in[18];
    const float* Wh1 = (const float*)d_in[19];
    const float* bh1 = (const float*)d_in[20];
    const float* Wh2 = (const float*)d_in[21];
    const float* bh2 = (const float*)d_in[22];
    float* out = (float*)d_out;

    float *agg, *bufA, *bufB, *invB, *pooled;
    int *cntB, *offB, *curB, *csrB, *bsumB, *bbaseB;
    cudaGetSymbolAddress((void**)&agg,    g_agg);
    cudaGetSymbolAddress((void**)&bufA,   g_bufA);
    cudaGetSymbolAddress((void**)&bufB,   g_bufB);
    cudaGetSymbolAddress((void**)&invB,   g_inv);
    cudaGetSymbolAddress((void**)&pooled, g_pooled);
    cudaGetSymbolAddress((void**)&cntB,   g_cnt);
    cudaGetSymbolAddress((void**)&offB,   g_off);
    cudaGetSymbolAddress((void**)&curB,   g_cur);
    cudaGetSymbolAddress((void**)&csrB,   g_csr);
    cudaGetSymbolAddress((void**)&bsumB,  g_bsum);
    cudaGetSymbolAddress((void**)&bbaseB, g_bbase);

    const int gemmBlocks = (NN + 127) / 128;

    zero_f4_kernel<<<1, 256>>>((float4*)pooled, TT * HH / 4);

    // ---- batched CSR build for all 8 timesteps ----
    zero_all_kernel<<<(TT * NN + 255) / 256, 256>>>(cntB, TT * NN);
    deg_all_kernel<<<(TT * EE + 255) / 256, 256>>>(ei, cntB);
    scan_reduce_all_kernel<<<TT * SCAN_BLOCKS, 256>>>(cntB, bsumB);
    scan_top_all_kernel<<<TT, 256>>>(bsumB, bbaseB);
    scan_final_all_kernel<<<TT * SCAN_BLOCKS, 256>>>(cntB, bbaseB, offB, curB, invB);
    fill_all_kernel<<<(TT * EE + 255) / 256, 256>>>(ei, curB, csrB);

    // ---- per-timestep fused layers ----
    for (int t = 0; t < TT; t++) {
        const float* x_t = xs + (size_t)t * NN * FF;
        const int* off = offB + (size_t)t * (NN + 1);
        const int* csr = csrB + (size_t)t * EE;
        const float* inv = invB + (size_t)t * NN;

        sage_fused_kernel<false><<<gemmBlocks, 256>>>(x_t, off, csr, inv, agg,
                                                      Wl1, Wr1, b1, bufA, NN);
        sage_fused_kernel<false><<<gemmBlocks, 256>>>(bufA, off, csr, inv, agg,
                                                      Wl2, Wr2, b2, bufB, NN);
        sage_fused_kernel<true><<<gemmBlocks, 256>>>(bufB, off, csr, inv, agg,
                                                     Wl3, Wr3, b3, pooled + t * HH, NN);
    }

    head_kernel<<<1, 128>>>(pooled, Wq, bq, Wk, bk, Wv, bv, Wo, bo, Wh1, bh1, Wh2, bh2, out);
}

// round 13
// speedup vs baseline: 1.7974x; 1.7974x over previous
#include <cuda_runtime.h>
#include <cuda_bf16.h>
#include <stdint.h>
#include <math.h>

#define TT 8
#define NN 50000
#define EE 800000
#define FF 128
#define HH 128
#define SCAN_BLOCKS ((NN + 255) / 256)   // 196

// ---------------- device scratch (no allocs allowed) ----------------
__device__ float g_agg[(size_t)NN * HH];
__device__ float g_bufA[(size_t)NN * HH];
__device__ float g_bufB[(size_t)NN * HH];
__device__ int   g_cnt[TT][NN];
__device__ int   g_off[TT][NN + 1];
__device__ int   g_cur[TT][NN];
__device__ int   g_csr[TT][EE];
__device__ int   g_bsum[TT][SCAN_BLOCKS];
__device__ int   g_bbase[TT][SCAN_BLOCKS];
__device__ float g_inv[TT][NN];
__device__ float g_pooled[TT * HH];

// ---------------- packed f32x2 helpers ----------------
__device__ __forceinline__ unsigned long long pack_dup(float a) {
    unsigned long long r;
    unsigned int au = __float_as_uint(a);
    asm("mov.b64 %0, {%1, %1};" : "=l"(r) : "r"(au));
    return r;
}
__device__ __forceinline__ void ffma2(unsigned long long& acc, unsigned long long a,
                                      unsigned long long b) {
    asm("fma.rn.f32x2 %0, %1, %2, %3;" : "=l"(acc) : "l"(a), "l"(b), "l"(acc));
}
__device__ __forceinline__ void unpack2(unsigned long long v, float& lo, float& hi) {
    unsigned int l, h;
    asm("mov.b64 {%0, %1}, %2;" : "=r"(l), "=r"(h) : "l"(v));
    lo = __uint_as_float(l);
    hi = __uint_as_float(h);
}

// ---------------- batched CSR utility kernels ----------------
__global__ void zero_all_kernel(int* __restrict__ p, int n) {
    int i = blockIdx.x * blockDim.x + threadIdx.x;
    if (i < n) p[i] = 0;
}
__global__ void zero_f4_kernel(float4* __restrict__ p, int n4) {
    int i = blockIdx.x * blockDim.x + threadIdx.x;
    if (i < n4) p[i] = make_float4(0.f, 0.f, 0.f, 0.f);
}

// all timesteps at once: cnt[t][dst]++
__global__ void deg_all_kernel(const int* __restrict__ ei, int* __restrict__ cntB) {
    int g = blockIdx.x * blockDim.x + threadIdx.x;
    if (g >= TT * EE) return;
    int t = g / EE;
    int e = g - t * EE;
    int d = ei[(size_t)t * 2 * EE + EE + e];
    atomicAdd(&cntB[t * NN + d], 1);
}

__global__ void scan_reduce_all_kernel(const int* __restrict__ cntB, int* __restrict__ bsumB) {
    __shared__ int wsum[8];
    int t = blockIdx.x / SCAN_BLOCKS;
    int blk = blockIdx.x - t * SCAN_BLOCKS;
    int i = blk * 256 + threadIdx.x;
    int v = (i < NN) ? cntB[t * NN + i] : 0;
    int lane = threadIdx.x & 31, wid = threadIdx.x >> 5;
    int s = v;
#pragma unroll
    for (int o = 16; o > 0; o >>= 1) s += __shfl_down_sync(0xffffffffu, s, o);
    if (lane == 0) wsum[wid] = s;
    __syncthreads();
    if (threadIdx.x == 0) {
        int tot = 0;
#pragma unroll
        for (int w = 0; w < 8; w++) tot += wsum[w];
        bsumB[t * SCAN_BLOCKS + blk] = tot;
    }
}

// grid = TT; each block scans its timestep's SCAN_BLOCKS partials
__global__ void scan_top_all_kernel(const int* __restrict__ bsumB, int* __restrict__ bbaseB) {
    __shared__ int wsum[8];
    int t = blockIdx.x;
    int tid = threadIdx.x;
    int v = (tid < SCAN_BLOCKS) ? bsumB[t * SCAN_BLOCKS + tid] : 0;
    int lane = tid & 31, wid = tid >> 5;
    int s = v;
#pragma unroll
    for (int o = 1; o < 32; o <<= 1) {
        int u = __shfl_up_sync(0xffffffffu, s, o);
        if (lane >= o) s += u;
    }
    if (lane == 31) wsum[wid] = s;
    __syncthreads();
    if (wid == 0) {
        int ws = (lane < 8) ? wsum[lane] : 0;
#pragma unroll
        for (int o = 1; o < 8; o <<= 1) {
            int u = __shfl_up_sync(0xffffffffu, ws, o);
            if (lane >= o) ws += u;
        }
        if (lane < 8) wsum[lane] = ws;
    }
    __syncthreads();
    int incl = s + (wid > 0 ? wsum[wid - 1] : 0);
    if (tid < SCAN_BLOCKS) bbaseB[t * SCAN_BLOCKS + tid] = incl - v;
}

__global__ void scan_final_all_kernel(const int* __restrict__ cntB, const int* __restrict__ bbaseB,
                                      int* __restrict__ offB, int* __restrict__ curB,
                                      float* __restrict__ invB) {
    __shared__ int wsum[8];
    int t = blockIdx.x / SCAN_BLOCKS;
    int blk = blockIdx.x - t * SCAN_BLOCKS;
    int i = blk * 256 + threadIdx.x;
    int v = (i < NN) ? cntB[t * NN + i] : 0;
    int lane = threadIdx.x & 31, wid = threadIdx.x >> 5;
    int s = v;
#pragma unroll
    for (int o = 1; o < 32; o <<= 1) {
        int u = __shfl_up_sync(0xffffffffu, s, o);
        if (lane >= o) s += u;
    }
    if (lane == 31) wsum[wid] = s;
    __syncthreads();
    if (wid == 0) {
        int ws = (lane < 8) ? wsum[lane] : 0;
#pragma unroll
        for (int o = 1; o < 8; o <<= 1) {
            int u = __shfl_up_sync(0xffffffffu, ws, o);
            if (lane >= o) ws += u;
        }
        if (lane < 8) wsum[lane] = ws;
    }
    __syncthreads();
    int excl = s - v + (wid > 0 ? wsum[wid - 1] : 0) + bbaseB[t * SCAN_BLOCKS + blk];
    if (i < NN) {
        offB[t * (NN + 1) + i] = excl;
        curB[t * NN + i] = excl;
        invB[t * NN + i] = 1.0f / (float)(v > 0 ? v : 1);
    }
    if (i == NN - 1) offB[t * (NN + 1) + NN] = excl + v;
}

__global__ void fill_all_kernel(const int* __restrict__ ei, int* __restrict__ curB,
                                int* __restrict__ csrB) {
    int g = blockIdx.x * blockDim.x + threadIdx.x;
    if (g >= TT * EE) return;
    int t = g / EE;
    int e = g - t * EE;
    const int* base = ei + (size_t)t * 2 * EE;
    int srcv = base[e];
    int d = base[EE + e];
    int p = atomicAdd(&curB[t * NN + d], 1);
    csrB[(size_t)t * EE + p] = srcv;
}

// ---------------- pull-side aggregation: one warp per dst node --------------
__global__ __launch_bounds__(256)
void agg_kernel(const float* __restrict__ x,
                const int* __restrict__ off,
                const int* __restrict__ csr,
                const float* __restrict__ inv,
                float* __restrict__ agg) {
    int node = (blockIdx.x * blockDim.x + threadIdx.x) >> 5;
    if (node >= NN) return;
    int lane = threadIdx.x & 31;
    int e = off[node];
    int e1 = off[node + 1];
    float4 acc = make_float4(0.f, 0.f, 0.f, 0.f);
    for (; e + 1 < e1; e += 2) {
        int s0 = csr[e];
        int s1 = csr[e + 1];
        float4 v0 = ((const float4*)(x + (size_t)s0 * HH))[lane];
        float4 v1 = ((const float4*)(x + (size_t)s1 * HH))[lane];
        acc.x += v0.x + v1.x;
        acc.y += v0.y + v1.y;
        acc.z += v0.z + v1.z;
        acc.w += v0.w + v1.w;
    }
    if (e < e1) {
        int s0 = csr[e];
        float4 v0 = ((const float4*)(x + (size_t)s0 * HH))[lane];
        acc.x += v0.x; acc.y += v0.y; acc.z += v0.z; acc.w += v0.w;
    }
    float sc = inv[node];
    acc.x *= sc; acc.y *= sc; acc.z *= sc; acc.w *= sc;
    ((float4*)(agg + (size_t)node * HH))[lane] = acc;
}

// ---------------- fused SAGE GEMM: FFMA2 + ping-pong smem double buffer ----------
// out = relu(aggS @ Wl + x @ Wr + b); tile 128x128, K=256, BK=16, 256 threads.
template<bool POOL>
__global__ __launch_bounds__(256, 2)
void sage_gemm_kernel(const float* __restrict__ A1,   // agg (scaled), K 0..127
                      const float* __restrict__ A2,   // x,            K 128..255
                      const float* __restrict__ Wl,
                      const float* __restrict__ Wr,
                      const float* __restrict__ bias,
                      float* __restrict__ out,
                      int n) {
    __shared__ float As[2][16][128];
    __shared__ float Bs[2][16][128];

    int tid = threadIdx.x;
    int tx = tid & 15;        // col group (8 cols = 4 f32x2)
    int ty = tid >> 4;        // row group (8 rows)
    int row0 = blockIdx.x * 128;

    int li = tid >> 2;          // A row 0..63 (+64)
    int lk = (tid & 3) * 4;     // A k sub 0,4,8,12
    int bk = tid >> 5;          // B k 0..7 (+8)
    int bj = (tid & 31) * 4;    // B col

    unsigned long long acc2[8][4];
#pragma unroll
    for (int r = 0; r < 8; r++)
#pragma unroll
        for (int c = 0; c < 4; c++) acc2[r][c] = 0ull;

    float4 rA0, rA1, rB0, rB1;

#define GLOAD(kt) do { \
        int k0 = (kt) * 16; \
        const float* Asrc = (k0 < 128) ? A1 : A2; \
        const float* Wsrc = (k0 < 128) ? Wl : Wr; \
        int ksrc = (k0 < 128) ? k0 : (k0 - 128); \
        int gi0 = row0 + li; \
        int gi1 = gi0 + 64; \
        rA0 = make_float4(0.f, 0.f, 0.f, 0.f); \
        rA1 = make_float4(0.f, 0.f, 0.f, 0.f); \
        if (gi0 < n) rA0 = *(const float4*)&Asrc[(size_t)gi0 * 128 + ksrc + lk]; \
        if (gi1 < n) rA1 = *(const float4*)&Asrc[(size_t)gi1 * 128 + ksrc + lk]; \
        rB0 = *(const float4*)&Wsrc[(size_t)(ksrc + bk) * 128 + bj]; \
        rB1 = *(const float4*)&Wsrc[(size_t)(ksrc + bk + 8) * 128 + bj]; \
    } while (0)

#define SSTORE(kt) do { \
        int b = (kt) & 1; \
        As[b][lk + 0][li] = rA0.x; As[b][lk + 1][li] = rA0.y; \
        As[b][lk + 2][li] = rA0.z; As[b][lk + 3][li] = rA0.w; \
        As[b][lk + 0][li + 64] = rA1.x; As[b][lk + 1][li + 64] = rA1.y; \
        As[b][lk + 2][li + 64] = rA1.z; As[b][lk + 3][li + 64] = rA1.w; \
        *(float4*)&Bs[b][bk][bj] = rB0; \
        *(float4*)&Bs[b][bk + 8][bj] = rB1; \
    } while (0)

    GLOAD(0);
    SSTORE(0);

#pragma unroll 1
    for (int kt = 0; kt < 16; kt++) {
        if (kt < 15) GLOAD(kt + 1);          // LDG for next tile (latency covered)
        __syncthreads();                     // current tile's STS visible
        int b = kt & 1;
#pragma unroll
        for (int k = 0; k < 16; k++) {
            float a[8];
            *(float4*)&a[0] = *(const float4*)&As[b][k][ty * 8];
            *(float4*)&a[4] = *(const float4*)&As[b][k][ty * 8 + 4];
            unsigned long long b2[4];
            const unsigned long long* bp = (const unsigned long long*)&Bs[b][k][tx * 8];
            b2[0] = bp[0]; b2[1] = bp[1]; b2[2] = bp[2]; b2[3] = bp[3];
#pragma unroll
            for (int r = 0; r < 8; r++) {
                unsigned long long aa = pack_dup(a[r]);
                ffma2(acc2[r][0], aa, b2[0]);
                ffma2(acc2[r][1], aa, b2[1]);
                ffma2(acc2[r][2], aa, b2[2]);
                ffma2(acc2[r][3], aa, b2[3]);
            }
        }
        if (kt < 15) SSTORE(kt + 1);         // other buffer; safe w/o extra sync
    }
    __syncthreads();

    float bv[8];
    *(float4*)&bv[0] = *(const float4*)&bias[tx * 8];
    *(float4*)&bv[4] = *(const float4*)&bias[tx * 8 + 4];

    if (!POOL) {
#pragma unroll
        for (int r = 0; r < 8; r++) {
            int gi = row0 + ty * 8 + r;
            if (gi < n) {
                float o[8];
#pragma unroll
                for (int c = 0; c < 4; c++) {
                    float lo, hi;
                    unpack2(acc2[r][c], lo, hi);
                    o[2 * c]     = fmaxf(lo + bv[2 * c], 0.f);
                    o[2 * c + 1] = fmaxf(hi + bv[2 * c + 1], 0.f);
                }
                *(float4*)&out[(size_t)gi * 128 + tx * 8]     = *(float4*)&o[0];
                *(float4*)&out[(size_t)gi * 128 + tx * 8 + 4] = *(float4*)&o[4];
            }
        }
    } else {
        float colsum[8];
#pragma unroll
        for (int c = 0; c < 8; c++) colsum[c] = 0.f;
#pragma unroll
        for (int r = 0; r < 8; r++) {
            int gi = row0 + ty * 8 + r;
            if (gi < n) {
#pragma unroll
                for (int c = 0; c < 4; c++) {
                    float lo, hi;
                    unpack2(acc2[r][c], lo, hi);
                    colsum[2 * c]     += fmaxf(lo + bv[2 * c], 0.f);
                    colsum[2 * c + 1] += fmaxf(hi + bv[2 * c + 1], 0.f);
                }
            }
        }
        float* red = &As[0][0][0];
        *(float4*)&red[ty * 128 + tx * 8]     = *(float4*)&colsum[0];
        *(float4*)&red[ty * 128 + tx * 8 + 4] = *(float4*)&colsum[4];
        __syncthreads();
        if (ty == 0) {
#pragma unroll
            for (int c = 0; c < 8; c++) {
                float s = 0.f;
#pragma unroll
                for (int g = 0; g < 16; g++) s += red[g * 128 + tx * 8 + c];
                atomicAdd(&out[tx * 8 + c], s);
            }
        }
    }
#undef GLOAD
#undef SSTORE
}

// ---------------- head: attention (only last q row) + MLP + sigmoid ----------------
__global__ void head_kernel(const float* __restrict__ pooled,
                            const float* __restrict__ Wq, const float* __restrict__ bq,
                            const float* __restrict__ Wk, const float* __restrict__ bk,
                            const float* __restrict__ Wv, const float* __restrict__ bv,
                            const float* __restrict__ Wo, const float* __restrict__ bo,
                            const float* __restrict__ Wh1, const float* __restrict__ bh1,
                            const float* __restrict__ Wh2, const float* __restrict__ bh2,
                            float* __restrict__ out) {
    __shared__ float seq[TT][HH];
    __shared__ float kk_s[TT][HH];
    __shared__ float vv_s[TT][HH];
    __shared__ float qv[HH];
    __shared__ float sc[4][TT];
    __shared__ float ol[HH];
    __shared__ float zz[HH];
    __shared__ float h1s[64];

    int j = threadIdx.x;  // 0..127
    const float invN = 1.0f / (float)NN;

    for (int t = 0; t < TT; t++) seq[t][j] = pooled[t * HH + j] * invN;
    __syncthreads();

    {
        float aq = bq[j];
        for (int k = 0; k < HH; k++) aq += seq[TT - 1][k] * Wq[k * HH + j];
        qv[j] = aq;
        for (int t = 0; t < TT; t++) {
            float ak = bk[j], av = bv[j];
            for (int k = 0; k < HH; k++) {
                float s = seq[t][k];
                ak += s * Wk[k * HH + j];
                av += s * Wv[k * HH + j];
            }
            kk_s[t][j] = ak;
            vv_s[t][j] = av;
        }
    }
    __syncthreads();

    if (j < 32) {
        int h = j >> 3, t = j & 7;
        float s = 0.f;
        for (int d = 0; d < 32; d++) s += qv[h * 32 + d] * kk_s[t][h * 32 + d];
        sc[h][t] = s * 0.17677669529663687f;
    }
    __syncthreads();
    if (j < 4) {
        float m = sc[j][0];
        for (int t = 1; t < TT; t++) m = fmaxf(m, sc[j][t]);
        float s = 0.f;
        for (int t = 0; t < TT; t++) { float e = expf(sc[j][t] - m); sc[j][t] = e; s += e; }
        float r = 1.0f / s;
        for (int t = 0; t < TT; t++) sc[j][t] *= r;
    }
    __syncthreads();

    {
        int h = j >> 5;
        float o = 0.f;
        for (int t = 0; t < TT; t++) o += sc[h][t] * vv_s[t][j];
        ol[j] = o;
    }
    __syncthreads();

    {
        float a = bo[j];
        for (int k = 0; k < HH; k++) a += ol[k] * Wo[k * HH + j];
        zz[j] = a;
    }
    __syncthreads();

    if (j < 64) {
        float a = bh1[j];
        for (int k = 0; k < HH; k++) a += zz[k] * Wh1[k * 64 + j];
        h1s[j] = fmaxf(a, 0.f);
    }
    __syncthreads();

    if (j == 0) {
        float a = bh2[0];
        for (int k = 0; k < 64; k++) a += h1s[k] * Wh2[k];
        out[0] = 1.0f / (1.0f + expf(-a));
    }
}

// ---------------- host ----------------
extern "C" void kernel_launch(void* const* d_in, const int* in_sizes, int n_in,
                              void* d_out, int out_size) {
    const float* xs  = (const float*)d_in[0];
    const int*   ei  = (const int*)d_in[1];
    const float* Wl1 = (const float*)d_in[2];
    const float* Wr1 = (const float*)d_in[3];
    const float* b1  = (const float*)d_in[4];
    const float* Wl2 = (const float*)d_in[5];
    const float* Wr2 = (const float*)d_in[6];
    const float* b2  = (const float*)d_in[7];
    const float* Wl3 = (const float*)d_in[8];
    const float* Wr3 = (const float*)d_in[9];
    const float* b3  = (const float*)d_in[10];
    const float* Wq  = (const float*)d_in[11];
    const float* bq  = (const float*)d_in[12];
    const float* Wk  = (const float*)d_in[13];
    const float* bk  = (const float*)d_in[14];
    const float* Wv  = (const float*)d_in[15];
    const float* bv  = (const float*)d_in[16];
    const float* Wo  = (const float*)d_in[17];
    const float* bo  = (const float*)d_in[18];
    const float* Wh1 = (const float*)d_in[19];
    const float* bh1 = (const float*)d_in[20];
    const float* Wh2 = (const float*)d_in[21];
    const float* bh2 = (const float*)d_in[22];
    float* out = (float*)d_out;

    float *agg, *bufA, *bufB, *invB, *pooled;
    int *cntB, *offB, *curB, *csrB, *bsumB, *bbaseB;
    cudaGetSymbolAddress((void**)&agg,    g_agg);
    cudaGetSymbolAddress((void**)&bufA,   g_bufA);
    cudaGetSymbolAddress((void**)&bufB,   g_bufB);
    cudaGetSymbolAddress((void**)&invB,   g_inv);
    cudaGetSymbolAddress((void**)&pooled, g_pooled);
    cudaGetSymbolAddress((void**)&cntB,   g_cnt);
    cudaGetSymbolAddress((void**)&offB,   g_off);
    cudaGetSymbolAddress((void**)&curB,   g_cur);
    cudaGetSymbolAddress((void**)&csrB,   g_csr);
    cudaGetSymbolAddress((void**)&bsumB,  g_bsum);
    cudaGetSymbolAddress((void**)&bbaseB, g_bbase);

    const int aggBlocks  = (NN * 32 + 255) / 256;
    const int gemmBlocks = (NN + 127) / 128;

    zero_f4_kernel<<<1, 256>>>((float4*)pooled, TT * HH / 4);

    // ---- batched CSR build for all 8 timesteps ----
    zero_all_kernel<<<(TT * NN + 255) / 256, 256>>>(cntB, TT * NN);
    deg_all_kernel<<<(TT * EE + 255) / 256, 256>>>(ei, cntB);
    scan_reduce_all_kernel<<<TT * SCAN_BLOCKS, 256>>>(cntB, bsumB);
    scan_top_all_kernel<<<TT, 256>>>(bsumB, bbaseB);
    scan_final_all_kernel<<<TT * SCAN_BLOCKS, 256>>>(cntB, bbaseB, offB, curB, invB);
    fill_all_kernel<<<(TT * EE + 255) / 256, 256>>>(ei, curB, csrB);

    // ---- per-timestep layers (separate agg for full occupancy) ----
    for (int t = 0; t < TT; t++) {
        const float* x_t = xs + (size_t)t * NN * FF;
        const int* off = offB + (size_t)t * (NN + 1);
        const int* csr = csrB + (size_t)t * EE;
        const float* inv = invB + (size_t)t * NN;

        agg_kernel<<<aggBlocks, 256>>>(x_t, off, csr, inv, agg);
        sage_gemm_kernel<false><<<gemmBlocks, 256>>>(agg, x_t, Wl1, Wr1, b1, bufA, NN);

        agg_kernel<<<aggBlocks, 256>>>(bufA, off, csr, inv, agg);
        sage_gemm_kernel<false><<<gemmBlocks, 256>>>(agg, bufA, Wl2, Wr2, b2, bufB, NN);

        agg_kernel<<<aggBlocks, 256>>>(bufB, off, csr, inv, agg);
        sage_gemm_kernel<true><<<gemmBlocks, 256>>>(agg, bufB, Wl3, Wr3, b3,
                                                    pooled + t * HH, NN);
    }

    head_kernel<<<1, 128>>>(pooled, Wq, bq, Wk, bk, Wv, bv, Wo, bo, Wh1, bh1, Wh2, bh2, out);
}

// round 14
// speedup vs baseline: 2.0875x; 1.1614x over previous
#include <cuda_runtime.h>
#include <cuda_bf16.h>
#include <stdint.h>
#include <math.h>

#define TT 8
#define NN 50000
#define EE 800000
#define FF 128
#define HH 128
#define SCAN_BLOCKS ((NN + 255) / 256)   // 196
#define GEMM_BLOCKS ((NN + 127) / 128)   // 391

// ---------------- device scratch (no allocs allowed) ----------------
__device__ float g_agg[TT][(size_t)NN * HH];
__device__ float g_bufA[TT][(size_t)NN * HH];
__device__ float g_bufB[TT][(size_t)NN * HH];
__device__ int   g_cnt[TT][NN];
__device__ int   g_off[TT][NN + 1];
__device__ int   g_cur[TT][NN];
__device__ int   g_csr[TT][EE];
__device__ int   g_bsum[TT][SCAN_BLOCKS];
__device__ int   g_bbase[TT][SCAN_BLOCKS];
__device__ float g_inv[TT][NN];
__device__ float g_pooled[TT * HH];

// ---------------- packed f32x2 helpers ----------------
__device__ __forceinline__ unsigned long long pack_dup(float a) {
    unsigned long long r;
    unsigned int au = __float_as_uint(a);
    asm("mov.b64 %0, {%1, %1};" : "=l"(r) : "r"(au));
    return r;
}
__device__ __forceinline__ void ffma2(unsigned long long& acc, unsigned long long a,
                                      unsigned long long b) {
    asm("fma.rn.f32x2 %0, %1, %2, %3;" : "=l"(acc) : "l"(a), "l"(b), "l"(acc));
}
__device__ __forceinline__ void unpack2(unsigned long long v, float& lo, float& hi) {
    unsigned int l, h;
    asm("mov.b64 {%0, %1}, %2;" : "=r"(l), "=r"(h) : "l"(v));
    lo = __uint_as_float(l);
    hi = __uint_as_float(h);
}

// ---------------- batched CSR utility kernels ----------------
__global__ void zero_all_kernel(int* __restrict__ p, int n) {
    int i = blockIdx.x * blockDim.x + threadIdx.x;
    if (i < n) p[i] = 0;
}
__global__ void zero_f4_kernel(float4* __restrict__ p, int n4) {
    int i = blockIdx.x * blockDim.x + threadIdx.x;
    if (i < n4) p[i] = make_float4(0.f, 0.f, 0.f, 0.f);
}

__global__ void deg_all_kernel(const int* __restrict__ ei, int* __restrict__ cntB) {
    int g = blockIdx.x * blockDim.x + threadIdx.x;
    if (g >= TT * EE) return;
    int t = g / EE;
    int e = g - t * EE;
    int d = ei[(size_t)t * 2 * EE + EE + e];
    atomicAdd(&cntB[t * NN + d], 1);
}

__global__ void scan_reduce_all_kernel(const int* __restrict__ cntB, int* __restrict__ bsumB) {
    __shared__ int wsum[8];
    int t = blockIdx.x / SCAN_BLOCKS;
    int blk = blockIdx.x - t * SCAN_BLOCKS;
    int i = blk * 256 + threadIdx.x;
    int v = (i < NN) ? cntB[t * NN + i] : 0;
    int lane = threadIdx.x & 31, wid = threadIdx.x >> 5;
    int s = v;
#pragma unroll
    for (int o = 16; o > 0; o >>= 1) s += __shfl_down_sync(0xffffffffu, s, o);
    if (lane == 0) wsum[wid] = s;
    __syncthreads();
    if (threadIdx.x == 0) {
        int tot = 0;
#pragma unroll
        for (int w = 0; w < 8; w++) tot += wsum[w];
        bsumB[t * SCAN_BLOCKS + blk] = tot;
    }
}

__global__ void scan_top_all_kernel(const int* __restrict__ bsumB, int* __restrict__ bbaseB) {
    __shared__ int wsum[8];
    int t = blockIdx.x;
    int tid = threadIdx.x;
    int v = (tid < SCAN_BLOCKS) ? bsumB[t * SCAN_BLOCKS + tid] : 0;
    int lane = tid & 31, wid = tid >> 5;
    int s = v;
#pragma unroll
    for (int o = 1; o < 32; o <<= 1) {
        int u = __shfl_up_sync(0xffffffffu, s, o);
        if (lane >= o) s += u;
    }
    if (lane == 31) wsum[wid] = s;
    __syncthreads();
    if (wid == 0) {
        int ws = (lane < 8) ? wsum[lane] : 0;
#pragma unroll
        for (int o = 1; o < 8; o <<= 1) {
            int u = __shfl_up_sync(0xffffffffu, ws, o);
            if (lane >= o) ws += u;
        }
        if (lane < 8) wsum[lane] = ws;
    }
    __syncthreads();
    int incl = s + (wid > 0 ? wsum[wid - 1] : 0);
    if (tid < SCAN_BLOCKS) bbaseB[t * SCAN_BLOCKS + tid] = incl - v;
}

__global__ void scan_final_all_kernel(const int* __restrict__ cntB, const int* __restrict__ bbaseB,
                                      int* __restrict__ offB, int* __restrict__ curB,
                                      float* __restrict__ invB) {
    __shared__ int wsum[8];
    int t = blockIdx.x / SCAN_BLOCKS;
    int blk = blockIdx.x - t * SCAN_BLOCKS;
    int i = blk * 256 + threadIdx.x;
    int v = (i < NN) ? cntB[t * NN + i] : 0;
    int lane = threadIdx.x & 31, wid = threadIdx.x >> 5;
    int s = v;
#pragma unroll
    for (int o = 1; o < 32; o <<= 1) {
        int u = __shfl_up_sync(0xffffffffu, s, o);
        if (lane >= o) s += u;
    }
    if (lane == 31) wsum[wid] = s;
    __syncthreads();
    if (wid == 0) {
        int ws = (lane < 8) ? wsum[lane] : 0;
#pragma unroll
        for (int o = 1; o < 8; o <<= 1) {
            int u = __shfl_up_sync(0xffffffffu, ws, o);
            if (lane >= o) ws += u;
        }
        if (lane < 8) wsum[lane] = ws;
    }
    __syncthreads();
    int excl = s - v + (wid > 0 ? wsum[wid - 1] : 0) + bbaseB[t * SCAN_BLOCKS + blk];
    if (i < NN) {
        offB[t * (NN + 1) + i] = excl;
        curB[t * NN + i] = excl;
        invB[t * NN + i] = 1.0f / (float)(v > 0 ? v : 1);
    }
    if (i == NN - 1) offB[t * (NN + 1) + NN] = excl + v;
}

__global__ void fill_all_kernel(const int* __restrict__ ei, int* __restrict__ curB,
                                int* __restrict__ csrB) {
    int g = blockIdx.x * blockDim.x + threadIdx.x;
    if (g >= TT * EE) return;
    int t = g / EE;
    int e = g - t * EE;
    const int* base = ei + (size_t)t * 2 * EE;
    int srcv = base[e];
    int d = base[EE + e];
    int p = atomicAdd(&curB[t * NN + d], 1);
    csrB[(size_t)t * EE + p] = srcv;
}

// ---------------- batched pull aggregation over ALL timesteps ----------------
// one warp per (t, node); x_t = xB + t*NN*HH
__global__ __launch_bounds__(256)
void agg_all_kernel(const float* __restrict__ xB,
                    const int* __restrict__ offB,
                    const int* __restrict__ csrB,
                    const float* __restrict__ invB,
                    float* __restrict__ aggB) {
    int w = (blockIdx.x * blockDim.x + threadIdx.x) >> 5;
    if (w >= TT * NN) return;
    int t = w / NN;
    int node = w - t * NN;
    int lane = threadIdx.x & 31;
    const float* x = xB + (size_t)t * NN * HH;
    const int* off = offB + (size_t)t * (NN + 1);
    const int* csr = csrB + (size_t)t * EE;
    int e = off[node];
    int e1 = off[node + 1];
    float4 acc = make_float4(0.f, 0.f, 0.f, 0.f);
    for (; e + 1 < e1; e += 2) {
        int s0 = csr[e];
        int s1 = csr[e + 1];
        float4 v0 = ((const float4*)(x + (size_t)s0 * HH))[lane];
        float4 v1 = ((const float4*)(x + (size_t)s1 * HH))[lane];
        acc.x += v0.x + v1.x;
        acc.y += v0.y + v1.y;
        acc.z += v0.z + v1.z;
        acc.w += v0.w + v1.w;
    }
    if (e < e1) {
        int s0 = csr[e];
        float4 v0 = ((const float4*)(x + (size_t)s0 * HH))[lane];
        acc.x += v0.x; acc.y += v0.y; acc.z += v0.z; acc.w += v0.w;
    }
    float sc = invB[t * NN + node];
    acc.x *= sc; acc.y *= sc; acc.z *= sc; acc.w *= sc;
    ((float4*)(aggB + (size_t)t * NN * HH + (size_t)node * HH))[lane] = acc;
}

// ---------------- batched SAGE GEMM over ALL timesteps ----------------
// blockIdx.x = t * GEMM_BLOCKS + blk ; out = relu(aggS @ Wl + x @ Wr + b)
template<bool POOL>
__global__ __launch_bounds__(256, 2)
void sage_gemm_all_kernel(const float* __restrict__ aggB,  // per-t agg (scaled)
                          const float* __restrict__ xB,    // per-t input
                          const float* __restrict__ Wl,
                          const float* __restrict__ Wr,
                          const float* __restrict__ bias,
                          float* __restrict__ outB) {      // !POOL: per-t N*H ; POOL: pooled (TT*HH)
    __shared__ float As[2][16][128];
    __shared__ float Bs[2][16][128];

    int t = blockIdx.x / GEMM_BLOCKS;
    int blk = blockIdx.x - t * GEMM_BLOCKS;
    const float* A1 = aggB + (size_t)t * NN * HH;
    const float* A2 = xB + (size_t)t * NN * HH;

    int tid = threadIdx.x;
    int tx = tid & 15;
    int ty = tid >> 4;
    int row0 = blk * 128;

    int li = tid >> 2;
    int lk = (tid & 3) * 4;
    int bk = tid >> 5;
    int bj = (tid & 31) * 4;

    unsigned long long acc2[8][4];
#pragma unroll
    for (int r = 0; r < 8; r++)
#pragma unroll
        for (int c = 0; c < 4; c++) acc2[r][c] = 0ull;

    float4 rA0, rA1, rB0, rB1;

#define GLOAD(kt) do { \
        int k0 = (kt) * 16; \
        const float* Asrc = (k0 < 128) ? A1 : A2; \
        const float* Wsrc = (k0 < 128) ? Wl : Wr; \
        int ksrc = (k0 < 128) ? k0 : (k0 - 128); \
        int gi0 = row0 + li; \
        int gi1 = gi0 + 64; \
        rA0 = make_float4(0.f, 0.f, 0.f, 0.f); \
        rA1 = make_float4(0.f, 0.f, 0.f, 0.f); \
        if (gi0 < NN) rA0 = *(const float4*)&Asrc[(size_t)gi0 * 128 + ksrc + lk]; \
        if (gi1 < NN) rA1 = *(const float4*)&Asrc[(size_t)gi1 * 128 + ksrc + lk]; \
        rB0 = *(const float4*)&Wsrc[(size_t)(ksrc + bk) * 128 + bj]; \
        rB1 = *(const float4*)&Wsrc[(size_t)(ksrc + bk + 8) * 128 + bj]; \
    } while (0)

#define SSTORE(kt) do { \
        int b = (kt) & 1; \
        As[b][lk + 0][li] = rA0.x; As[b][lk + 1][li] = rA0.y; \
        As[b][lk + 2][li] = rA0.z; As[b][lk + 3][li] = rA0.w; \
        As[b][lk + 0][li + 64] = rA1.x; As[b][lk + 1][li + 64] = rA1.y; \
        As[b][lk + 2][li + 64] = rA1.z; As[b][lk + 3][li + 64] = rA1.w; \
        *(float4*)&Bs[b][bk][bj] = rB0; \
        *(float4*)&Bs[b][bk + 8][bj] = rB1; \
    } while (0)

    GLOAD(0);
    SSTORE(0);

#pragma unroll 1
    for (int kt = 0; kt < 16; kt++) {
        if (kt < 15) GLOAD(kt + 1);
        __syncthreads();
        int b = kt & 1;
#pragma unroll
        for (int k = 0; k < 16; k++) {
            float a[8];
            *(float4*)&a[0] = *(const float4*)&As[b][k][ty * 8];
            *(float4*)&a[4] = *(const float4*)&As[b][k][ty * 8 + 4];
            unsigned long long b2[4];
            const unsigned long long* bp = (const unsigned long long*)&Bs[b][k][tx * 8];
            b2[0] = bp[0]; b2[1] = bp[1]; b2[2] = bp[2]; b2[3] = bp[3];
#pragma unroll
            for (int r = 0; r < 8; r++) {
                unsigned long long aa = pack_dup(a[r]);
                ffma2(acc2[r][0], aa, b2[0]);
                ffma2(acc2[r][1], aa, b2[1]);
                ffma2(acc2[r][2], aa, b2[2]);
                ffma2(acc2[r][3], aa, b2[3]);
            }
        }
        if (kt < 15) SSTORE(kt + 1);
    }
    __syncthreads();

    float bv[8];
    *(float4*)&bv[0] = *(const float4*)&bias[tx * 8];
    *(float4*)&bv[4] = *(const float4*)&bias[tx * 8 + 4];

    if (!POOL) {
        float* out = outB + (size_t)t * NN * HH;
#pragma unroll
        for (int r = 0; r < 8; r++) {
            int gi = row0 + ty * 8 + r;
            if (gi < NN) {
                float o[8];
#pragma unroll
                for (int c = 0; c < 4; c++) {
                    float lo, hi;
                    unpack2(acc2[r][c], lo, hi);
                    o[2 * c]     = fmaxf(lo + bv[2 * c], 0.f);
                    o[2 * c + 1] = fmaxf(hi + bv[2 * c + 1], 0.f);
                }
                *(float4*)&out[(size_t)gi * 128 + tx * 8]     = *(float4*)&o[0];
                *(float4*)&out[(size_t)gi * 128 + tx * 8 + 4] = *(float4*)&o[4];
            }
        }
    } else {
        float* out = outB + t * HH;     // pooled slot for this timestep
        float colsum[8];
#pragma unroll
        for (int c = 0; c < 8; c++) colsum[c] = 0.f;
#pragma unroll
        for (int r = 0; r < 8; r++) {
            int gi = row0 + ty * 8 + r;
            if (gi < NN) {
#pragma unroll
                for (int c = 0; c < 4; c++) {
                    float lo, hi;
                    unpack2(acc2[r][c], lo, hi);
                    colsum[2 * c]     += fmaxf(lo + bv[2 * c], 0.f);
                    colsum[2 * c + 1] += fmaxf(hi + bv[2 * c + 1], 0.f);
                }
            }
        }
        float* red = &As[0][0][0];
        *(float4*)&red[ty * 128 + tx * 8]     = *(float4*)&colsum[0];
        *(float4*)&red[ty * 128 + tx * 8 + 4] = *(float4*)&colsum[4];
        __syncthreads();
        if (ty == 0) {
#pragma unroll
            for (int c = 0; c < 8; c++) {
                float s = 0.f;
#pragma unroll
                for (int g = 0; g < 16; g++) s += red[g * 128 + tx * 8 + c];
                atomicAdd(&out[tx * 8 + c], s);
            }
        }
    }
#undef GLOAD
#undef SSTORE
}

// ---------------- head: attention (only last q row) + MLP + sigmoid ----------------
__global__ void head_kernel(const float* __restrict__ pooled,
                            const float* __restrict__ Wq, const float* __restrict__ bq,
                            const float* __restrict__ Wk, const float* __restrict__ bk,
                            const float* __restrict__ Wv, const float* __restrict__ bv,
                            const float* __restrict__ Wo, const float* __restrict__ bo,
                            const float* __restrict__ Wh1, const float* __restrict__ bh1,
                            const float* __restrict__ Wh2, const float* __restrict__ bh2,
                            float* __restrict__ out) {
    __shared__ float seq[TT][HH];
    __shared__ float kk_s[TT][HH];
    __shared__ float vv_s[TT][HH];
    __shared__ float qv[HH];
    __shared__ float sc[4][TT];
    __shared__ float ol[HH];
    __shared__ float zz[HH];
    __shared__ float h1s[64];

    int j = threadIdx.x;  // 0..127
    const float invN = 1.0f / (float)NN;

    for (int t = 0; t < TT; t++) seq[t][j] = pooled[t * HH + j] * invN;
    __syncthreads();

    {
        float aq = bq[j];
        for (int k = 0; k < HH; k++) aq += seq[TT - 1][k] * Wq[k * HH + j];
        qv[j] = aq;
        for (int t = 0; t < TT; t++) {
            float ak = bk[j], av = bv[j];
            for (int k = 0; k < HH; k++) {
                float s = seq[t][k];
                ak += s * Wk[k * HH + j];
                av += s * Wv[k * HH + j];
            }
            kk_s[t][j] = ak;
            vv_s[t][j] = av;
        }
    }
    __syncthreads();

    if (j < 32) {
        int h = j >> 3, t = j & 7;
        float s = 0.f;
        for (int d = 0; d < 32; d++) s += qv[h * 32 + d] * kk_s[t][h * 32 + d];
        sc[h][t] = s * 0.17677669529663687f;
    }
    __syncthreads();
    if (j < 4) {
        float m = sc[j][0];
        for (int t = 1; t < TT; t++) m = fmaxf(m, sc[j][t]);
        float s = 0.f;
        for (int t = 0; t < TT; t++) { float e = expf(sc[j][t] - m); sc[j][t] = e; s += e; }
        float r = 1.0f / s;
        for (int t = 0; t < TT; t++) sc[j][t] *= r;
    }
    __syncthreads();

    {
        int h = j >> 5;
        float o = 0.f;
        for (int t = 0; t < TT; t++) o += sc[h][t] * vv_s[t][j];
        ol[j] = o;
    }
    __syncthreads();

    {
        float a = bo[j];
        for (int k = 0; k < HH; k++) a += ol[k] * Wo[k * HH + j];
        zz[j] = a;
    }
    __syncthreads();

    if (j < 64) {
        float a = bh1[j];
        for (int k = 0; k < HH; k++) a += zz[k] * Wh1[k * 64 + j];
        h1s[j] = fmaxf(a, 0.f);
    }
    __syncthreads();

    if (j == 0) {
        float a = bh2[0];
        for (int k = 0; k < 64; k++) a += h1s[k] * Wh2[k];
        out[0] = 1.0f / (1.0f + expf(-a));
    }
}

// ---------------- host ----------------
extern "C" void kernel_launch(void* const* d_in, const int* in_sizes, int n_in,
                              void* d_out, int out_size) {
    const float* xs  = (const float*)d_in[0];
    const int*   ei  = (const int*)d_in[1];
    const float* Wl1 = (const float*)d_in[2];
    const float* Wr1 = (const float*)d_in[3];
    const float* b1  = (const float*)d_in[4];
    const float* Wl2 = (const float*)d_in[5];
    const float* Wr2 = (const float*)d_in[6];
    const float* b2  = (const float*)d_in[7];
    const float* Wl3 = (const float*)d_in[8];
    const float* Wr3 = (const float*)d_in[9];
    const float* b3  = (const float*)d_in[10];
    const float* Wq  = (const float*)d_in[11];
    const float* bq  = (const float*)d_in[12];
    const float* Wk  = (const float*)d_in[13];
    const float* bk  = (const float*)d_in[14];
    const float* Wv  = (const float*)d_in[15];
    const float* bv  = (const float*)d_in[16];
    const float* Wo  = (const float*)d_in[17];
    const float* bo  = (const float*)d_in[18];
    const float* Wh1 = (const float*)d_in[19];
    const float* bh1 = (const float*)d_in[20];
    const float* Wh2 = (const float*)d_in[21];
    const float* bh2 = (const float*)d_in[22];
    float* out = (float*)d_out;

    float *aggB, *bufAB, *bufBB, *invB, *pooled;
    int *cntB, *offB, *curB, *csrB, *bsumB, *bbaseB;
    cudaGetSymbolAddress((void**)&aggB,   g_agg);
    cudaGetSymbolAddress((void**)&bufAB,  g_bufA);
    cudaGetSymbolAddress((void**)&bufBB,  g_bufB);
    cudaGetSymbolAddress((void**)&invB,   g_inv);
    cudaGetSymbolAddress((void**)&pooled, g_pooled);
    cudaGetSymbolAddress((void**)&cntB,   g_cnt);
    cudaGetSymbolAddress((void**)&offB,   g_off);
    cudaGetSymbolAddress((void**)&curB,   g_cur);
    cudaGetSymbolAddress((void**)&csrB,   g_csr);
    cudaGetSymbolAddress((void**)&bsumB,  g_bsum);
    cudaGetSymbolAddress((void**)&bbaseB, g_bbase);

    const int aggAllBlocks = (TT * NN * 32 + 255) / 256;   // 50000 blocks
    const int gemmAllBlocks = TT * GEMM_BLOCKS;            // 3128 blocks

    zero_f4_kernel<<<1, 256>>>((float4*)pooled, TT * HH / 4);

    // ---- batched CSR build for all 8 timesteps ----
    zero_all_kernel<<<(TT * NN + 255) / 256, 256>>>(cntB, TT * NN);
    deg_all_kernel<<<(TT * EE + 255) / 256, 256>>>(ei, cntB);
    scan_reduce_all_kernel<<<TT * SCAN_BLOCKS, 256>>>(cntB, bsumB);
    scan_top_all_kernel<<<TT, 256>>>(bsumB, bbaseB);
    scan_final_all_kernel<<<TT * SCAN_BLOCKS, 256>>>(cntB, bbaseB, offB, curB, invB);
    fill_all_kernel<<<(TT * EE + 255) / 256, 256>>>(ei, curB, csrB);

    // ---- layer passes, each batched over all 8 timesteps ----
    // layer 1: input xs
    agg_all_kernel<<<aggAllBlocks, 256>>>(xs, offB, csrB, invB, aggB);
    sage_gemm_all_kernel<false><<<gemmAllBlocks, 256>>>(aggB, xs, Wl1, Wr1, b1, bufAB);

    // layer 2: input bufA
    agg_all_kernel<<<aggAllBlocks, 256>>>(bufAB, offB, csrB, invB, aggB);
    sage_gemm_all_kernel<false><<<gemmAllBlocks, 256>>>(aggB, bufAB, Wl2, Wr2, b2, bufBB);

    // layer 3: input bufB, output pooled (column sums)
    agg_all_kernel<<<aggAllBlocks, 256>>>(bufBB, offB, csrB, invB, aggB);
    sage_gemm_all_kernel<true><<<gemmAllBlocks, 256>>>(aggB, bufBB, Wl3, Wr3, b3, pooled);

    head_kernel<<<1, 128>>>(pooled, Wq, bq, Wk, bk, Wv, bv, Wo, bo, Wh1, bh1, Wh2, bh2, out);
}

// round 17
// speedup vs baseline: 3.0091x; 1.4415x over previous
#include <cuda_runtime.h>
#include <cuda_bf16.h>
#include <stdint.h>
#include <math.h>

#define TT 8
#define NN 50000
#define EE 800000
#define FF 128
#define HH 128
#define SCAN_BLOCKS ((NN + 255) / 256)   // 196
#define GEMM_BLOCKS ((NN + 127) / 128)   // 391
#define KSTRIDE 132

// ---------------- device scratch (no allocs allowed) ----------------
__device__ float g_agg[TT][(size_t)NN * HH];
__device__ float g_bufA[TT][(size_t)NN * HH];
__device__ float g_bufB[TT][(size_t)NN * HH];
__device__ int   g_cnt[TT][NN];
__device__ int   g_off[TT][NN + 1];
__device__ int   g_cur[TT][NN];
__device__ int   g_csr[TT][EE];
__device__ int   g_bsum[TT][SCAN_BLOCKS];
__device__ int   g_bbase[TT][SCAN_BLOCKS];
__device__ float g_inv[TT][NN];
__device__ float g_pooled[TT * HH];

// ---------------- helpers ----------------
__device__ __forceinline__ uint32_t tf32r(float x) {
    float r;
    asm("cvt.rna.tf32.f32 %0, %1;" : "=f"(r) : "f"(x));
    return __float_as_uint(r);
}

__device__ __forceinline__ void mma_tf32(float* c, const uint32_t* a, const uint32_t* b) {
    asm volatile(
        "mma.sync.aligned.m16n8k8.row.col.f32.tf32.tf32.f32 "
        "{%0,%1,%2,%3}, {%4,%5,%6,%7}, {%8,%9}, {%0,%1,%2,%3};"
        : "+f"(c[0]), "+f"(c[1]), "+f"(c[2]), "+f"(c[3])
        : "r"(a[0]), "r"(a[1]), "r"(a[2]), "r"(a[3]), "r"(b[0]), "r"(b[1]));
}

// ---------------- batched CSR utility kernels ----------------
__global__ void zero_all_kernel(int* __restrict__ p, int n) {
    int i = blockIdx.x * blockDim.x + threadIdx.x;
    if (i < n) p[i] = 0;
}
__global__ void zero_f4_kernel(float4* __restrict__ p, int n4) {
    int i = blockIdx.x * blockDim.x + threadIdx.x;
    if (i < n4) p[i] = make_float4(0.f, 0.f, 0.f, 0.f);
}

__global__ void deg_all_kernel(const int* __restrict__ ei, int* __restrict__ cntB) {
    int g = blockIdx.x * blockDim.x + threadIdx.x;
    if (g >= TT * EE) return;
    int t = g / EE;
    int e = g - t * EE;
    int d = ei[(size_t)t * 2 * EE + EE + e];
    atomicAdd(&cntB[t * NN + d], 1);
}

__global__ void scan_reduce_all_kernel(const int* __restrict__ cntB, int* __restrict__ bsumB) {
    __shared__ int wsum[8];
    int t = blockIdx.x / SCAN_BLOCKS;
    int blk = blockIdx.x - t * SCAN_BLOCKS;
    int i = blk * 256 + threadIdx.x;
    int v = (i < NN) ? cntB[t * NN + i] : 0;
    int lane = threadIdx.x & 31, wid = threadIdx.x >> 5;
    int s = v;
#pragma unroll
    for (int o = 16; o > 0; o >>= 1) s += __shfl_down_sync(0xffffffffu, s, o);
    if (lane == 0) wsum[wid] = s;
    __syncthreads();
    if (threadIdx.x == 0) {
        int tot = 0;
#pragma unroll
        for (int w = 0; w < 8; w++) tot += wsum[w];
        bsumB[t * SCAN_BLOCKS + blk] = tot;
    }
}

__global__ void scan_top_all_kernel(const int* __restrict__ bsumB, int* __restrict__ bbaseB) {
    __shared__ int wsum[8];
    int t = blockIdx.x;
    int tid = threadIdx.x;
    int v = (tid < SCAN_BLOCKS) ? bsumB[t * SCAN_BLOCKS + tid] : 0;
    int lane = tid & 31, wid = tid >> 5;
    int s = v;
#pragma unroll
    for (int o = 1; o < 32; o <<= 1) {
        int u = __shfl_up_sync(0xffffffffu, s, o);
        if (lane >= o) s += u;
    }
    if (lane == 31) wsum[wid] = s;
    __syncthreads();
    if (wid == 0) {
        int ws = (lane < 8) ? wsum[lane] : 0;
#pragma unroll
        for (int o = 1; o < 8; o <<= 1) {
            int u = __shfl_up_sync(0xffffffffu, ws, o);
            if (lane >= o) ws += u;
        }
        if (lane < 8) wsum[lane] = ws;
    }
    __syncthreads();
    int incl = s + (wid > 0 ? wsum[wid - 1] : 0);
    if (tid < SCAN_BLOCKS) bbaseB[t * SCAN_BLOCKS + tid] = incl - v;
}

__global__ void scan_final_all_kernel(const int* __restrict__ cntB, const int* __restrict__ bbaseB,
                                      int* __restrict__ offB, int* __restrict__ curB,
                                      float* __restrict__ invB) {
    __shared__ int wsum[8];
    int t = blockIdx.x / SCAN_BLOCKS;
    int blk = blockIdx.x - t * SCAN_BLOCKS;
    int i = blk * 256 + threadIdx.x;
    int v = (i < NN) ? cntB[t * NN + i] : 0;
    int lane = threadIdx.x & 31, wid = threadIdx.x >> 5;
    int s = v;
#pragma unroll
    for (int o = 1; o < 32; o <<= 1) {
        int u = __shfl_up_sync(0xffffffffu, s, o);
        if (lane >= o) s += u;
    }
    if (lane == 31) wsum[wid] = s;
    __syncthreads();
    if (wid == 0) {
        int ws = (lane < 8) ? wsum[lane] : 0;
#pragma unroll
        for (int o = 1; o < 8; o <<= 1) {
            int u = __shfl_up_sync(0xffffffffu, ws, o);
            if (lane >= o) ws += u;
        }
        if (lane < 8) wsum[lane] = ws;
    }
    __syncthreads();
    int excl = s - v + (wid > 0 ? wsum[wid - 1] : 0) + bbaseB[t * SCAN_BLOCKS + blk];
    if (i < NN) {
        offB[t * (NN + 1) + i] = excl;
        curB[t * NN + i] = excl;
        invB[t * NN + i] = 1.0f / (float)(v > 0 ? v : 1);
    }
    if (i == NN - 1) offB[t * (NN + 1) + NN] = excl + v;
}

__global__ void fill_all_kernel(const int* __restrict__ ei, int* __restrict__ curB,
                                int* __restrict__ csrB) {
    int g = blockIdx.x * blockDim.x + threadIdx.x;
    if (g >= TT * EE) return;
    int t = g / EE;
    int e = g - t * EE;
    const int* base = ei + (size_t)t * 2 * EE;
    int srcv = base[e];
    int d = base[EE + e];
    int p = atomicAdd(&curB[t * NN + d], 1);
    csrB[(size_t)t * EE + p] = srcv;
}

// ---------------- batched pull aggregation over ALL timesteps ----------------
__global__ __launch_bounds__(256)
void agg_all_kernel(const float* __restrict__ xB,
                    const int* __restrict__ offB,
                    const int* __restrict__ csrB,
                    const float* __restrict__ invB,
                    float* __restrict__ aggB) {
    int w = (blockIdx.x * blockDim.x + threadIdx.x) >> 5;
    if (w >= TT * NN) return;
    int t = w / NN;
    int node = w - t * NN;
    int lane = threadIdx.x & 31;
    const float* x = xB + (size_t)t * NN * HH;
    const int* off = offB + (size_t)t * (NN + 1);
    const int* csr = csrB + (size_t)t * EE;
    int e = off[node];
    int e1 = off[node + 1];
    float4 acc = make_float4(0.f, 0.f, 0.f, 0.f);
    for (; e + 1 < e1; e += 2) {
        int s0 = csr[e];
        int s1 = csr[e + 1];
        float4 v0 = ((const float4*)(x + (size_t)s0 * HH))[lane];
        float4 v1 = ((const float4*)(x + (size_t)s1 * HH))[lane];
        acc.x += v0.x + v1.x;
        acc.y += v0.y + v1.y;
        acc.z += v0.z + v1.z;
        acc.w += v0.w + v1.w;
    }
    if (e < e1) {
        int s0 = csr[e];
        float4 v0 = ((const float4*)(x + (size_t)s0 * HH))[lane];
        acc.x += v0.x; acc.y += v0.y; acc.z += v0.z; acc.w += v0.w;
    }
    float sc = invB[t * NN + node];
    acc.x *= sc; acc.y *= sc; acc.z *= sc; acc.w *= sc;
    ((float4*)(aggB + (size_t)t * NN * HH + (size_t)node * HH))[lane] = acc;
}

// ---------------- batched SAGE GEMM via mma.sync tf32 ----------------
// blockIdx.x = t * GEMM_BLOCKS + blk ; out = relu(aggS @ Wl + x @ Wr + b)
// tile 128x128, K=256, BK=16, 256 thr = 8 warps; warp tile 32m x 64n of m16n8k8.
template<bool POOL>
__global__ __launch_bounds__(256, 2)
void sage_mma_all_kernel(const float* __restrict__ aggB,
                         const float* __restrict__ xB,
                         const float* __restrict__ Wl,
                         const float* __restrict__ Wr,
                         const float* __restrict__ bias,
                         float* __restrict__ outB) {
    __shared__ float As[2][16][KSTRIDE];   // As[buf][k][m] (tf32 bits)
    __shared__ float Bs[2][16][KSTRIDE];   // Bs[buf][k][n] (tf32 bits)
    __shared__ float biasS[128];
    __shared__ float pool[128];

    int t = blockIdx.x / GEMM_BLOCKS;
    int blk = blockIdx.x - t * GEMM_BLOCKS;
    const float* A1 = aggB + (size_t)t * NN * HH;
    const float* A2 = xB + (size_t)t * NN * HH;

    int tid = threadIdx.x;
    int wid = tid >> 5;
    int lane = tid & 31;
    int gid = lane >> 2;       // 0..7
    int tig = lane & 3;        // 0..3
    int row0 = blk * 128;

    int m_base = (wid & 3) * 32;
    int n_base = (wid >> 2) * 64;

    // loader roles
    int li = tid >> 2;          // A row 0..63 (+64)
    int lk = (tid & 3) * 4;     // A k sub 0,4,8,12
    int bk = tid >> 5;          // B k 0..7 (+8)
    int bj = (tid & 31) * 4;    // B col

    if (tid < 128) {
        biasS[tid] = bias[tid];
        pool[tid] = 0.f;
    }

    float acc[2][8][4];
#pragma unroll
    for (int mt = 0; mt < 2; mt++)
#pragma unroll
        for (int nt = 0; nt < 8; nt++)
#pragma unroll
            for (int i = 0; i < 4; i++) acc[mt][nt][i] = 0.f;

    float4 rA0, rA1, rB0, rB1;

#define GLOAD(kt) do { \
        int k0 = (kt) * 16; \
        const float* Asrc = (k0 < 128) ? A1 : A2; \
        const float* Wsrc = (k0 < 128) ? Wl : Wr; \
        int ksrc = (k0 < 128) ? k0 : (k0 - 128); \
        int gi0 = row0 + li; \
        int gi1 = gi0 + 64; \
        rA0 = make_float4(0.f, 0.f, 0.f, 0.f); \
        rA1 = make_float4(0.f, 0.f, 0.f, 0.f); \
        if (gi0 < NN) rA0 = *(const float4*)&Asrc[(size_t)gi0 * 128 + ksrc + lk]; \
        if (gi1 < NN) rA1 = *(const float4*)&Asrc[(size_t)gi1 * 128 + ksrc + lk]; \
        rB0 = *(const float4*)&Wsrc[(size_t)(ksrc + bk) * 128 + bj]; \
        rB1 = *(const float4*)&Wsrc[(size_t)(ksrc + bk + 8) * 128 + bj]; \
    } while (0)

#define SSTORE(kt) do { \
        int b = (kt) & 1; \
        As[b][lk + 0][li] = __uint_as_float(tf32r(rA0.x)); \
        As[b][lk + 1][li] = __uint_as_float(tf32r(rA0.y)); \
        As[b][lk + 2][li] = __uint_as_float(tf32r(rA0.z)); \
        As[b][lk + 3][li] = __uint_as_float(tf32r(rA0.w)); \
        As[b][lk + 0][li + 64] = __uint_as_float(tf32r(rA1.x)); \
        As[b][lk + 1][li + 64] = __uint_as_float(tf32r(rA1.y)); \
        As[b][lk + 2][li + 64] = __uint_as_float(tf32r(rA1.z)); \
        As[b][lk + 3][li + 64] = __uint_as_float(tf32r(rA1.w)); \
        float4 cv0, cv1; \
        cv0.x = __uint_as_float(tf32r(rB0.x)); cv0.y = __uint_as_float(tf32r(rB0.y)); \
        cv0.z = __uint_as_float(tf32r(rB0.z)); cv0.w = __uint_as_float(tf32r(rB0.w)); \
        cv1.x = __uint_as_float(tf32r(rB1.x)); cv1.y = __uint_as_float(tf32r(rB1.y)); \
        cv1.z = __uint_as_float(tf32r(rB1.z)); cv1.w = __uint_as_float(tf32r(rB1.w)); \
        *(float4*)&Bs[b][bk][bj] = cv0; \
        *(float4*)&Bs[b][bk + 8][bj] = cv1; \
    } while (0)

    GLOAD(0);
    SSTORE(0);

#pragma unroll 1
    for (int kt = 0; kt < 16; kt++) {
        if (kt < 15) GLOAD(kt + 1);
        __syncthreads();
        int b = kt & 1;
#pragma unroll
        for (int kk = 0; kk < 16; kk += 8) {
            // A fragments: 2 m16 tiles
            uint32_t af[2][4];
#pragma unroll
            for (int mt = 0; mt < 2; mt++) {
                int m0 = m_base + mt * 16 + gid;
                af[mt][0] = __float_as_uint(As[b][kk + tig][m0]);
                af[mt][1] = __float_as_uint(As[b][kk + tig][m0 + 8]);
                af[mt][2] = __float_as_uint(As[b][kk + tig + 4][m0]);
                af[mt][3] = __float_as_uint(As[b][kk + tig + 4][m0 + 8]);
            }
            // B fragments: 8 n8 tiles
            uint32_t bf[8][2];
#pragma unroll
            for (int nt = 0; nt < 8; nt++) {
                int n0 = n_base + nt * 8 + gid;
                bf[nt][0] = __float_as_uint(Bs[b][kk + tig][n0]);
                bf[nt][1] = __float_as_uint(Bs[b][kk + tig + 4][n0]);
            }
#pragma unroll
            for (int mt = 0; mt < 2; mt++)
#pragma unroll
                for (int nt = 0; nt < 8; nt++)
                    mma_tf32(acc[mt][nt], af[mt], bf[nt]);
        }
        if (kt < 15) SSTORE(kt + 1);
    }
    __syncthreads();

    // epilogue: c0=(gid,2tig) c1=(gid,2tig+1) c2=(gid+8,2tig) c3=(gid+8,2tig+1)
    if (!POOL) {
        float* out = outB + (size_t)t * NN * HH;
#pragma unroll
        for (int mt = 0; mt < 2; mt++) {
#pragma unroll
            for (int half = 0; half < 2; half++) {
                int gi = row0 + m_base + mt * 16 + gid + half * 8;
                if (gi < NN) {
#pragma unroll
                    for (int nt = 0; nt < 8; nt++) {
                        int col = n_base + nt * 8 + 2 * tig;
                        float2 v;
                        v.x = fmaxf(acc[mt][nt][half * 2 + 0] + biasS[col], 0.f);
                        v.y = fmaxf(acc[mt][nt][half * 2 + 1] + biasS[col + 1], 0.f);
                        *(float2*)&out[(size_t)gi * 128 + col] = v;
                    }
                }
            }
        }
    } else {
        float* out = outB + t * HH;
#pragma unroll
        for (int nt = 0; nt < 8; nt++) {
            int col = n_base + nt * 8 + 2 * tig;
            float s0 = 0.f, s1 = 0.f;
#pragma unroll
            for (int mt = 0; mt < 2; mt++) {
#pragma unroll
                for (int half = 0; half < 2; half++) {
                    int gi = row0 + m_base + mt * 16 + gid + half * 8;
                    if (gi < NN) {
                        s0 += fmaxf(acc[mt][nt][half * 2 + 0] + biasS[col], 0.f);
                        s1 += fmaxf(acc[mt][nt][half * 2 + 1] + biasS[col + 1], 0.f);
                    }
                }
            }
            atomicAdd(&pool[col], s0);
            atomicAdd(&pool[col + 1], s1);
        }
        __syncthreads();
        if (tid < 128) atomicAdd(&out[tid], pool[tid]);
    }
#undef GLOAD
#undef SSTORE
}

// ---------------- head: attention (only last q row) + MLP + sigmoid ----------------
__global__ void head_kernel(const float* __restrict__ pooled,
                            const float* __restrict__ Wq, const float* __restrict__ bq,
                            const float* __restrict__ Wk, const float* __restrict__ bk,
                            const float* __restrict__ Wv, const float* __restrict__ bv,
                            const float* __restrict__ Wo, const float* __restrict__ bo,
                            const float* __restrict__ Wh1, const float* __restrict__ bh1,
                            const float* __restrict__ Wh2, const float* __restrict__ bh2,
                            float* __restrict__ out) {
    __shared__ float seq[TT][HH];
    __shared__ float kk_s[TT][HH];
    __shared__ float vv_s[TT][HH];
    __shared__ float qv[HH];
    __shared__ float sc[4][TT];
    __shared__ float ol[HH];
    __shared__ float zz[HH];
    __shared__ float h1s[64];

    int j = threadIdx.x;  // 0..127
    const float invN = 1.0f / (float)NN;

    for (int t = 0; t < TT; t++) seq[t][j] = pooled[t * HH + j] * invN;
    __syncthreads();

    {
        float aq = bq[j];
        for (int k = 0; k < HH; k++) aq += seq[TT - 1][k] * Wq[k * HH + j];
        qv[j] = aq;
        for (int t = 0; t < TT; t++) {
            float ak = bk[j], av = bv[j];
            for (int k = 0; k < HH; k++) {
                float s = seq[t][k];
                ak += s * Wk[k * HH + j];
                av += s * Wv[k * HH + j];
            }
            kk_s[t][j] = ak;
            vv_s[t][j] = av;
        }
    }
    __syncthreads();

    if (j < 32) {
        int h = j >> 3, t = j & 7;
        float s = 0.f;
        for (int d = 0; d < 32; d++) s += qv[h * 32 + d] * kk_s[t][h * 32 + d];
        sc[h][t] = s * 0.17677669529663687f;
    }
    __syncthreads();
    if (j < 4) {
        float m = sc[j][0];
        for (int t = 1; t < TT; t++) m = fmaxf(m, sc[j][t]);
        float s = 0.f;
        for (int t = 0; t < TT; t++) { float e = expf(sc[j][t] - m); sc[j][t] = e; s += e; }
        float r = 1.0f / s;
        for (int t = 0; t < TT; t++) sc[j][t] *= r;
    }
    __syncthreads();

    {
        int h = j >> 5;
        float o = 0.f;
        for (int t = 0; t < TT; t++) o += sc[h][t] * vv_s[t][j];
        ol[j] = o;
    }
    __syncthreads();

    {
        float a = bo[j];
        for (int k = 0; k < HH; k++) a += ol[k] * Wo[k * HH + j];
        zz[j] = a;
    }
    __syncthreads();

    if (j < 64) {
        float a = bh1[j];
        for (int k = 0; k < HH; k++) a += zz[k] * Wh1[k * 64 + j];
        h1s[j] = fmaxf(a, 0.f);
    }
    __syncthreads();

    if (j == 0) {
        float a = bh2[0];
        for (int k = 0; k < 64; k++) a += h1s[k] * Wh2[k];
        out[0] = 1.0f / (1.0f + expf(-a));
    }
}

// ---------------- host ----------------
extern "C" void kernel_launch(void* const* d_in, const int* in_sizes, int n_in,
                              void* d_out, int out_size) {
    const float* xs  = (const float*)d_in[0];
    const int*   ei  = (const int*)d_in[1];
    const float* Wl1 = (const float*)d_in[2];
    const float* Wr1 = (const float*)d_in[3];
    const float* b1  = (const float*)d_in[4];
    const float* Wl2 = (const float*)d_in[5];
    const float* Wr2 = (const float*)d_in[6];
    const float* b2  = (const float*)d_in[7];
    const float* Wl3 = (const float*)d_in[8];
    const float* Wr3 = (const float*)d_in[9];
    const float* b3  = (const float*)d_in[10];
    const float* Wq  = (const float*)d_in[11];
    const float* bq  = (const float*)d_in[12];
    const float* Wk  = (const float*)d_in[13];
    const float* bk  = (const float*)d_in[14];
    const float* Wv  = (const float*)d_in[15];
    const float* bv  = (const float*)d_in[16];
    const float* Wo  = (const float*)d_in[17];
    const float* bo  = (const float*)d_in[18];
    const float* Wh1 = (const float*)d_in[19];
    const float* bh1 = (const float*)d_in[20];
    const float* Wh2 = (const float*)d_in[21];
    const float* bh2 = (const float*)d_in[22];
    float* out = (float*)d_out;

    float *aggB, *bufAB, *bufBB, *invB, *pooled;
    int *cntB, *offB, *curB, *csrB, *bsumB, *bbaseB;
    cudaGetSymbolAddress((void**)&aggB,   g_agg);
    cudaGetSymbolAddress((void**)&bufAB,  g_bufA);
    cudaGetSymbolAddress((void**)&bufBB,  g_bufB);
    cudaGetSymbolAddress((void**)&invB,   g_inv);
    cudaGetSymbolAddress((void**)&pooled, g_pooled);
    cudaGetSymbolAddress((void**)&cntB,   g_cnt);
    cudaGetSymbolAddress((void**)&offB,   g_off);
    cudaGetSymbolAddress((void**)&curB,   g_cur);
    cudaGetSymbolAddress((void**)&csrB,   g_csr);
    cudaGetSymbolAddress((void**)&bsumB,  g_bsum);
    cudaGetSymbolAddress((void**)&bbaseB, g_bbase);

    const int aggAllBlocks = (TT * NN * 32 + 255) / 256;
    const int gemmAllBlocks = TT * GEMM_BLOCKS;

    zero_f4_kernel<<<1, 256>>>((float4*)pooled, TT * HH / 4);

    // ---- batched CSR build for all 8 timesteps ----
    zero_all_kernel<<<(TT * NN + 255) / 256, 256>>>(cntB, TT * NN);
    deg_all_kernel<<<(TT * EE + 255) / 256, 256>>>(ei, cntB);
    scan_reduce_all_kernel<<<TT * SCAN_BLOCKS, 256>>>(cntB, bsumB);
    scan_top_all_kernel<<<TT, 256>>>(bsumB, bbaseB);
    scan_final_all_kernel<<<TT * SCAN_BLOCKS, 256>>>(cntB, bbaseB, offB, curB, invB);
    fill_all_kernel<<<(TT * EE + 255) / 256, 256>>>(ei, curB, csrB);

    // ---- layer passes, each batched over all 8 timesteps ----
    agg_all_kernel<<<aggAllBlocks, 256>>>(xs, offB, csrB, invB, aggB);
    sage_mma_all_kernel<false><<<gemmAllBlocks, 256>>>(aggB, xs, Wl1, Wr1, b1, bufAB);

    agg_all_kernel<<<aggAllBlocks, 256>>>(bufAB, offB, csrB, invB, aggB);
    sage_mma_all_kernel<false><<<gemmAllBlocks, 256>>>(aggB, bufAB, Wl2, Wr2, b2, bufBB);

    agg_all_kernel<<<aggAllBlocks, 256>>>(bufBB, offB, csrB, invB, aggB);
    sage_mma_all_kernel<true><<<gemmAllBlocks, 256>>>(aggB, bufBB, Wl3, Wr3, b3, pooled);

    head_kernel<<<1, 128>>>(pooled, Wq, bq, Wk, bk, Wv, bv, Wo, bo, Wh1, bh1, Wh2, bh2, out);
}